// round 1
// baseline (speedup 1.0000x reference)
#include <cuda_runtime.h>

#define BATCH   16
#define CHN     512
#define HW      4096           // 64*64
#define NCLS    5
#define NSEG    (BATCH * NCLS) // 80
#define NPIX    (BATCH * HW)   // 65536
#define CCHUNKS 8
#define CPER    (CHN / CCHUNKS) // 64
#define BETA    2.0f
#define EPS2    (0.001f * 0.001f)

__device__ float g_loss[NPIX];     // sum over channels of squared diff (NOT yet /C)
__device__ float g_segsum[NSEG];
__device__ float g_segcnt[NSEG];
__device__ float g_avg[NSEG];
__device__ float g_wmax;

// ---------------------------------------------------------------- kernel 1
__global__ void frl_zero(float* __restrict__ out) {
    int i = blockIdx.x * blockDim.x + threadIdx.x;
    if (i < NPIX) g_loss[i] = 0.0f;
    if (i < NSEG) { g_segsum[i] = 0.0f; g_segcnt[i] = 0.0f; }
    if (i == 0) out[0] = 0.0f;
}

// ---------------------------------------------------------------- kernel 2
// grid = BATCH * CCHUNKS * 4 = 512 blocks, 256 threads.
// Each thread owns one float4 (4 pixels) and a 64-channel slice; accumulates
// squared diffs in registers, then 4 spread atomic adds.
__global__ void frl_mse(const float4* __restrict__ rec,
                        const float4* __restrict__ ali) {
    const int bid  = blockIdx.x;
    const int jblk = bid & 3;          // 4 j-blocks of 256 float4s
    const int k    = (bid >> 2) & 7;   // channel chunk
    const int b    = bid >> 5;         // batch
    const int j    = jblk * 256 + threadIdx.x;   // 0..1023 float4 within image
    const int imgStride = HW / 4;                // 1024 float4 per channel-plane

    int base = (b * CHN + k * CPER) * imgStride + j;

    float ax = 0.f, ay = 0.f, az = 0.f, aw = 0.f;
    #pragma unroll 4
    for (int c = 0; c < CPER; ++c) {
        float4 r = rec[base + c * imgStride];
        float4 a = ali[base + c * imgStride];
        float dx = r.x - a.x, dy = r.y - a.y, dz = r.z - a.z, dw = r.w - a.w;
        ax += dx * dx; ay += dy * dy; az += dz * dz; aw += dw * dw;
    }

    float* lp = &g_loss[b * HW + j * 4];
    atomicAdd(lp + 0, ax);
    atomicAdd(lp + 1, ay);
    atomicAdd(lp + 2, az);
    atomicAdd(lp + 3, aw);
}

// ---------------------------------------------------------------- kernel 3
// 80-bin histogram of loss_metric (=g_loss/C) sums + counts per (b, class).
__global__ void frl_seg(const int* __restrict__ mask) {
    __shared__ float ssum[NSEG];
    __shared__ float scnt[NSEG];
    const int t = threadIdx.x;
    if (t < NSEG) { ssum[t] = 0.0f; scnt[t] = 0.0f; }
    __syncthreads();

    const int stride = gridDim.x * blockDim.x;
    for (int p = blockIdx.x * blockDim.x + t; p < NPIX; p += stride) {
        int b   = p >> 12;                 // p / HW
        int seg = b * NCLS + mask[p];
        atomicAdd(&ssum[seg], g_loss[p] * (1.0f / CHN));
        atomicAdd(&scnt[seg], 1.0f);
    }
    __syncthreads();
    if (t < NSEG) {
        atomicAdd(&g_segsum[t], ssum[t]);
        atomicAdd(&g_segcnt[t], scnt[t]);
    }
}

// ---------------------------------------------------------------- kernel 4
// Single block: per-segment mean, then max over segments.
__global__ void frl_avg() {
    __shared__ float smax[128];
    const int t = threadIdx.x;
    float v = 0.0f;
    if (t < NSEG) {
        float a = g_segsum[t] / fmaxf(g_segcnt[t], 1.0f);
        g_avg[t] = a;
        v = a;   // empty segments contribute 0; loss>=0 so max is unaffected
    }
    smax[t] = v;
    __syncthreads();
    #pragma unroll
    for (int s = 64; s > 0; s >>= 1) {
        if (t < s) smax[t] = fmaxf(smax[t], smax[t + s]);
        __syncthreads();
    }
    if (t == 0) g_wmax = smax[0];
}

// ---------------------------------------------------------------- kernel 5
// Weighted mean: out += sum_p lm_p * (clip(w_p)*BETA + 1) / NPIX
__global__ void frl_final(const int* __restrict__ mask, float* __restrict__ out) {
    const float wmax = g_wmax;
    const float inv  = 1.0f / (wmax + EPS2);
    const bool  pos  = (wmax > 0.0f);

    float acc = 0.0f;
    const int stride = gridDim.x * blockDim.x;
    for (int p = blockIdx.x * blockDim.x + threadIdx.x; p < NPIX; p += stride) {
        int b   = p >> 12;
        float a = g_avg[b * NCLS + mask[p]];
        float w = pos ? a * inv : a + EPS2;
        w = fminf(fmaxf(w, 0.0f), 1.0f);
        float lm = g_loss[p] * (1.0f / CHN);
        acc += lm * (w * BETA + 1.0f);
    }

    // warp reduce
    #pragma unroll
    for (int off = 16; off > 0; off >>= 1)
        acc += __shfl_xor_sync(0xFFFFFFFFu, acc, off);

    __shared__ float swarp[8];
    const int lane = threadIdx.x & 31;
    const int wid  = threadIdx.x >> 5;
    if (lane == 0) swarp[wid] = acc;
    __syncthreads();
    if (wid == 0) {
        float v = (lane < (blockDim.x >> 5)) ? swarp[lane] : 0.0f;
        #pragma unroll
        for (int off = 4; off > 0; off >>= 1)
            v += __shfl_xor_sync(0xFFFFFFFFu, v, off);
        if (lane == 0)
            atomicAdd(out, v * (1.0f / NPIX));
    }
}

// ---------------------------------------------------------------- launch
extern "C" void kernel_launch(void* const* d_in, const int* in_sizes, int n_in,
                              void* d_out, int out_size) {
    const float4* rec  = (const float4*)d_in[0];
    const float4* ali  = (const float4*)d_in[1];
    const int*    mask = (const int*)d_in[2];
    float*        out  = (float*)d_out;

    frl_zero<<<(NPIX + 255) / 256, 256>>>(out);
    frl_mse<<<BATCH * CCHUNKS * 4, 256>>>(rec, ali);
    frl_seg<<<128, 256>>>(mask);
    frl_avg<<<1, 128>>>();
    frl_final<<<128, 256>>>(mask, out);
}